// round 13
// baseline (speedup 1.0000x reference)
#include <cuda_runtime.h>
#include <cuda_bf16.h>

// LRN spatial 5x5: out = x / (2 + 1e-4 * boxsum5x5(x^2))^0.75
// x: (16, 96, 224, 224) fp32, zero padding.
//
// R13 = R12 (smem tile + float4-per-thread separable stencil, exact-width
//       LDS, Taylor d^-0.75, __stcs) + 6 blocks/SM:
//   - __launch_bounds__(224, 6): 48-reg budget -> 1344 thr/SM (65% occ)
//   - phase-A indexing hoisted (224 = 4*56 -> row = tid/56 + 4k exactly;
//     one div/mod + pointer walk instead of 9 div/mod pairs)
//   - bx folded into the xr ring (one fewer live float4)

#define LRN_W   224
#define LRN_H   224
#define LRN_R   8                    // rows per row-group
#define LRN_RG  4                    // row-groups per block
#define LRN_TH  (LRN_R * LRN_RG)     // 32 output rows per block
#define LRN_TR  (LRN_TH + 4)         // 36 tile rows
#define LRN_XSW 232                  // 4 pad + 224 + 4 pad
#define LRN_CG  56                   // col-groups per row

// d^-0.75 Taylor around ssq=0 (d=2):  a0 + a1*s + a2*s^2, trunc < 1e-6 rel
#define LRN_A0  0.59460355750136051f
#define LRN_A1  (-2.2297633406301019e-05f)
#define LRN_A2  9.7552395902567078e-10f

__device__ __forceinline__ float lrn_norm(float s) {
    return fmaf(s, fmaf(s, LRN_A2, LRN_A1), LRN_A0);
}

// Horizontal 5-tap ssq for 4 cols (xs idx = global col + 4).
// Exact-width loads: LDS.64 @ g4+2, LDS.128 @ g4+4 (own), LDS.64 @ g4+8.
__device__ __forceinline__ float4 hsum_row(const float* __restrict__ rowp,
                                           int g4, float4* __restrict__ bx) {
    float2 l = *reinterpret_cast<const float2*>(rowp + g4 + 2);
    float4 b = *reinterpret_cast<const float4*>(rowp + g4 + 4);
    float2 r = *reinterpret_cast<const float2*>(rowp + g4 + 8);
    *bx = b;
    float ql0 = l.x * l.x, ql1 = l.y * l.y;
    float q0 = b.x * b.x, q1 = b.y * b.y;
    float q2 = b.z * b.z, q3 = b.w * b.w;
    float qr0 = r.x * r.x, qr1 = r.y * r.y;
    float4 h;
    h.x = ql0 + ql1 + q0 + q1 + q2;
    h.y = h.x - ql0 + q3;
    h.z = h.y - ql1 + qr0;
    h.w = h.z - q0 + qr1;
    return h;
}

__global__ __launch_bounds__(224, 6)
void lrn_kernel(const float* __restrict__ x, float* __restrict__ out) {
    __shared__ float xs[LRN_TR][LRN_XSW];   // global col c -> idx c+4

    const int plane = blockIdx.x;                 // n*96 + c
    const int r0    = blockIdx.y * LRN_TH;        // 0,32,...,192
    const int tid   = threadIdx.x;
    const int g     = tid % LRN_CG;               // col-group 0..55
    const int rg    = tid / LRN_CG;               // 0..3 (also phase-A row0)
    const int g4    = g * 4;
    const float* __restrict__ px   = x   + (size_t)plane * (LRN_H * LRN_W);
    float*       __restrict__ pout = out + (size_t)plane * (LRN_H * LRN_W);

    // ---- Phase A: coalesced float4 tile load (rows r0-2 .. r0+33) ----
    // 224 = 4*56 -> thread's k-th group is tile row rg + 4k, fixed col g4.
    {
        const float* src = px + (size_t)(r0 - 2 + rg) * LRN_W + g4;
        float* dst = &xs[rg][4 + g4];
        #pragma unroll
        for (int k = 0; k < LRN_TR / 4; ++k) {    // 9 groups per thread
            int grow = r0 - 2 + rg + 4 * k;
            float4 v = make_float4(0.f, 0.f, 0.f, 0.f);
            if (grow >= 0 && grow < LRN_H)
                v = *reinterpret_cast<const float4*>(src);
            *reinterpret_cast<float4*>(dst) = v;
            src += 4 * LRN_W;
            dst += 4 * LRN_XSW;
        }
    }
    // zero column pads (idx 2,3 = cols -2,-1; idx 228,229 = cols 224,225)
    if (tid < LRN_TR * 4) {
        int row = tid >> 2;
        int j   = tid & 3;
        int idx = (j < 2) ? (2 + j) : (226 + j);
        xs[row][idx] = 0.f;
    }
    __syncthreads();

    // ---- Stream phase: 56 col-groups x 4 row-groups ----
    const int ti0 = rg * LRN_R + 2;          // tile row of first output row
    const int sr0 = r0 + rg * LRN_R;         // global first output row

    float4 hist[4];
    float4 xr[2];
    float4 t;
    hist[0] = hsum_row(&xs[ti0 - 2][0], g4, &t);
    hist[1] = hsum_row(&xs[ti0 - 1][0], g4, &t);
    hist[2] = hsum_row(&xs[ti0    ][0], g4, &xr[0]);
    hist[3] = hsum_row(&xs[ti0 + 1][0], g4, &xr[1]);

    float4 vs;
    vs.x = hist[0].x + hist[1].x + hist[2].x + hist[3].x;
    vs.y = hist[0].y + hist[1].y + hist[2].y + hist[3].y;
    vs.z = hist[0].z + hist[1].z + hist[2].z + hist[3].z;
    vs.w = hist[0].w + hist[1].w + hist[2].w + hist[3].w;

    float* po = pout + (size_t)sr0 * LRN_W + g4;

    #pragma unroll
    for (int i = 0; i < LRN_R; ++i) {
        float4 xnew;
        float4 hnew = hsum_row(&xs[ti0 + 2 + i][0], g4, &xnew);

        float4 vf;                           // vertical 5-tap ssq @ row sr0+i
        vf.x = vs.x + hnew.x;
        vf.y = vs.y + hnew.y;
        vf.z = vs.z + hnew.z;
        vf.w = vs.w + hnew.w;

        float4 xa = xr[i & 1];               // raw x @ row sr0+i
        float4 val;
        val.x = xa.x * lrn_norm(vf.x);
        val.y = xa.y * lrn_norm(vf.y);
        val.z = xa.z * lrn_norm(vf.z);
        val.w = xa.w * lrn_norm(vf.w);

        __stcs(reinterpret_cast<float4*>(po), val);
        po += LRN_W;

        float4 hold = hist[i & 3];           // h @ row sr0+i-2
        vs.x = vf.x - hold.x;
        vs.y = vf.y - hold.y;
        vs.z = vf.z - hold.z;
        vs.w = vf.w - hold.w;
        hist[i & 3] = hnew;
        xr[i & 1] = xnew;
    }
}

extern "C" void kernel_launch(void* const* d_in, const int* in_sizes, int n_in,
                              void* d_out, int out_size) {
    const float* x = (const float*)d_in[0];
    float* out = (float*)d_out;
    (void)in_sizes; (void)n_in; (void)out_size;
    dim3 grid(16 * 96, LRN_H / LRN_TH);    // 1536 planes x 7 row-strips
    lrn_kernel<<<grid, 224>>>(x, out);
}

// round 14
// speedup vs baseline: 1.2451x; 1.2451x over previous
#include <cuda_runtime.h>
#include <cuda_bf16.h>

// LRN spatial 5x5: out = x / (2 + 1e-4 * boxsum5x5(x^2))^0.75
// x: (16, 96, 224, 224) fp32, zero padding.
//
// R14 = R12 (best measured: smem tile + float4-per-thread separable
//       stencil, exact-width LDS, Taylor d^-0.75, __stcs, 5 blocks/SM)
//       with phase A cleaned WITHOUT tightening the register budget
//       (R13 showed a 48-reg cap destroys phase-A MLP):
//   - block-uniform specialization: interior row-strips (5 of 7) load the
//     tile with an unchecked, fully-batched 9x LDG.128 pointer walk;
//     only the first/last strips run the bounds-checked path
//   - pointer-walk addressing replaces 9 div/mod pairs per thread

#define LRN_W   224
#define LRN_H   224
#define LRN_R   8                    // rows per row-group
#define LRN_RG  4                    // row-groups per block
#define LRN_TH  (LRN_R * LRN_RG)     // 32 output rows per block
#define LRN_TR  (LRN_TH + 4)         // 36 tile rows
#define LRN_XSW 232                  // 4 pad + 224 + 4 pad
#define LRN_CG  56                   // col-groups per row

// d^-0.75 Taylor around ssq=0 (d=2): a0 + a1*s + a2*s^2, trunc < 1e-6 rel
#define LRN_A0  0.59460355750136051f
#define LRN_A1  (-2.2297633406301019e-05f)
#define LRN_A2  9.7552395902567078e-10f

__device__ __forceinline__ float lrn_norm(float s) {
    return fmaf(s, fmaf(s, LRN_A2, LRN_A1), LRN_A0);
}

// Horizontal 5-tap ssq for 4 cols (xs idx = global col + 4).
// Exact-width loads: LDS.64 @ g4+2, LDS.128 @ g4+4 (own), LDS.64 @ g4+8.
__device__ __forceinline__ float4 hsum_row(const float* __restrict__ rowp,
                                           int g4, float4* __restrict__ bx) {
    float2 l = *reinterpret_cast<const float2*>(rowp + g4 + 2);
    float4 b = *reinterpret_cast<const float4*>(rowp + g4 + 4);
    float2 r = *reinterpret_cast<const float2*>(rowp + g4 + 8);
    *bx = b;
    float ql0 = l.x * l.x, ql1 = l.y * l.y;
    float q0 = b.x * b.x, q1 = b.y * b.y;
    float q2 = b.z * b.z, q3 = b.w * b.w;
    float qr0 = r.x * r.x, qr1 = r.y * r.y;
    float4 h;
    h.x = ql0 + ql1 + q0 + q1 + q2;
    h.y = h.x - ql0 + q3;
    h.z = h.y - ql1 + qr0;
    h.w = h.z - q0 + qr1;
    return h;
}

__global__ __launch_bounds__(224, 5)
void lrn_kernel(const float* __restrict__ x, float* __restrict__ out) {
    __shared__ float xs[LRN_TR][LRN_XSW];   // global col c -> idx c+4

    const int plane = blockIdx.x;                 // n*96 + c
    const int r0    = blockIdx.y * LRN_TH;        // 0,32,...,192
    const int tid   = threadIdx.x;
    const int g     = tid % LRN_CG;               // col-group 0..55
    const int rg    = tid / LRN_CG;               // 0..3 (also phase-A row0)
    const int g4    = g * 4;
    const float* __restrict__ px   = x   + (size_t)plane * (LRN_H * LRN_W);
    float*       __restrict__ pout = out + (size_t)plane * (LRN_H * LRN_W);

    // ---- Phase A: float4 tile load, rows r0-2 .. r0+33 ----
    // Thread's k-th group = tile row rg + 4k, fixed column g4.
    {
        const float* src = px + (ptrdiff_t)(r0 - 2 + rg) * LRN_W + g4;
        float* dst = &xs[rg][4 + g4];
        if (blockIdx.y != 0 && blockIdx.y != gridDim.y - 1) {
            // Interior strip: all 36 tile rows in-plane; unchecked batch.
            #pragma unroll
            for (int k = 0; k < LRN_TR / 4; ++k) {    // 9 loads
                *reinterpret_cast<float4*>(dst) =
                    *reinterpret_cast<const float4*>(src);
                src += 4 * LRN_W;
                dst += 4 * LRN_XSW;
            }
        } else {
            // Edge strip: rows may fall outside the plane -> checked.
            #pragma unroll
            for (int k = 0; k < LRN_TR / 4; ++k) {
                int grow = r0 - 2 + rg + 4 * k;
                float4 v = make_float4(0.f, 0.f, 0.f, 0.f);
                if (grow >= 0 && grow < LRN_H)
                    v = *reinterpret_cast<const float4*>(src);
                *reinterpret_cast<float4*>(dst) = v;
                src += 4 * LRN_W;
                dst += 4 * LRN_XSW;
            }
        }
    }
    // zero column pads (idx 2,3 = cols -2,-1; idx 228,229 = cols 224,225)
    if (tid < LRN_TR * 4) {
        int row = tid >> 2;
        int j   = tid & 3;
        int idx = (j < 2) ? (2 + j) : (226 + j);
        xs[row][idx] = 0.f;
    }
    __syncthreads();

    // ---- Stream phase: 56 col-groups x 4 row-groups ----
    const int ti0 = rg * LRN_R + 2;          // tile row of first output row
    const int sr0 = r0 + rg * LRN_R;         // global first output row

    float4 hist[4];
    float4 xr[2];
    float4 t;
    hist[0] = hsum_row(&xs[ti0 - 2][0], g4, &t);
    hist[1] = hsum_row(&xs[ti0 - 1][0], g4, &t);
    hist[2] = hsum_row(&xs[ti0    ][0], g4, &xr[0]);
    hist[3] = hsum_row(&xs[ti0 + 1][0], g4, &xr[1]);

    float4 vs;
    vs.x = hist[0].x + hist[1].x + hist[2].x + hist[3].x;
    vs.y = hist[0].y + hist[1].y + hist[2].y + hist[3].y;
    vs.z = hist[0].z + hist[1].z + hist[2].z + hist[3].z;
    vs.w = hist[0].w + hist[1].w + hist[2].w + hist[3].w;

    float* po = pout + (size_t)sr0 * LRN_W + g4;

    #pragma unroll
    for (int i = 0; i < LRN_R; ++i) {
        float4 xnew;
        float4 hnew = hsum_row(&xs[ti0 + 2 + i][0], g4, &xnew);

        float4 vf;                           // vertical 5-tap ssq @ row sr0+i
        vf.x = vs.x + hnew.x;
        vf.y = vs.y + hnew.y;
        vf.z = vs.z + hnew.z;
        vf.w = vs.w + hnew.w;

        float4 xa = xr[i & 1];               // raw x @ row sr0+i
        float4 val;
        val.x = xa.x * lrn_norm(vf.x);
        val.y = xa.y * lrn_norm(vf.y);
        val.z = xa.z * lrn_norm(vf.z);
        val.w = xa.w * lrn_norm(vf.w);

        __stcs(reinterpret_cast<float4*>(po), val);
        po += LRN_W;

        float4 hold = hist[i & 3];           // h @ row sr0+i-2
        vs.x = vf.x - hold.x;
        vs.y = vf.y - hold.y;
        vs.z = vf.z - hold.z;
        vs.w = vf.w - hold.w;
        hist[i & 3] = hnew;
        xr[i & 1] = xnew;
    }
}

extern "C" void kernel_launch(void* const* d_in, const int* in_sizes, int n_in,
                              void* d_out, int out_size) {
    const float* x = (const float*)d_in[0];
    float* out = (float*)d_out;
    (void)in_sizes; (void)n_in; (void)out_size;
    dim3 grid(16 * 96, LRN_H / LRN_TH);    // 1536 planes x 7 row-strips
    lrn_kernel<<<grid, 224>>>(x, out);
}

// round 15
// speedup vs baseline: 1.2698x; 1.0198x over previous
#include <cuda_runtime.h>
#include <cuda_bf16.h>
#include <cstdint>

// LRN spatial 5x5: out = x / (2 + 1e-4 * boxsum5x5(x^2))^0.75
// x: (16, 96, 224, 224) fp32, zero padding.
//
// R15: async double-buffered tile pipeline.
//   A 32-row tile of one plane is CONTIGUOUS in gmem (28672 B) -> one
//   cp.async.bulk (UBLKCP) per tile, issued by thread 0 into alternating
//   smem buffers with mbarrier complete_tx. While warps compute tile t,
//   the bulk engine loads tile t+1 -> DRAM never idles during compute
//   (R12/R14's load/compute alternation was capping dram__cycles at ~76%).
//   Block = 112 rows = 4 tiles of 28 output rows; 224 threads.
//   Compute core = R12/R14 (measured best): exact-width LDS horizontal
//   5-tap sliding ssq, vertical 5-tap register ring, Taylor d^-0.75,
//   __stcs stores. Row halo OOB: bulk copy clipped + h zeroed by predicate.
//   Column halo: predicated edge LDS (no pad columns; tile width = 224).

#define LRN_W   224
#define LRN_H   224
#define LRN_TH  28                     // output rows per tile
#define LRN_TR  32                     // tile rows incl. 2+2 halo
#define LRN_NT  4                      // tiles per block (112 rows)
#define LRN_CG  56                     // col-groups (4 cols each)
#define LRN_R   7                      // rows per row-group (4 groups)
#define LRN_TILE_FLOATS (LRN_TR * LRN_W)        // 7168
#define LRN_TILE_BYTES  (LRN_TILE_FLOATS * 4)   // 28672
#define LRN_ROWB        (LRN_W * 4)             // 896

// d^-0.75 Taylor around ssq=0 (d=2): a0 + a1*s + a2*s^2, trunc < 1e-6 rel
#define LRN_A0  0.59460355750136051f
#define LRN_A1  (-2.2297633406301019e-05f)
#define LRN_A2  9.7552395902567078e-10f

__device__ __forceinline__ float lrn_norm(float s) {
    return fmaf(s, fmaf(s, LRN_A2, LRN_A1), LRN_A0);
}

// Horizontal 5-tap ssq for 4 cols at row pointer rowp (tile row, width 224).
// gl/gr: column-halo validity (predicated edge loads stay in-bounds).
// ok: row inside the plane -> otherwise h forced to zero (smem row may be
// unwritten; its b value is never consumed for invalid rows).
__device__ __forceinline__ float4 hsum_row(const float* __restrict__ rowp,
                                           int g4, bool gl, bool gr, bool ok,
                                           float4* __restrict__ bx) {
    float4 b = *reinterpret_cast<const float4*>(rowp + g4);
    float2 l = gl ? *reinterpret_cast<const float2*>(rowp + g4 - 2)
                  : make_float2(0.f, 0.f);
    float2 r = gr ? *reinterpret_cast<const float2*>(rowp + g4 + 4)
                  : make_float2(0.f, 0.f);
    *bx = b;
    float ql0 = l.x * l.x, ql1 = l.y * l.y;
    float q0 = b.x * b.x, q1 = b.y * b.y;
    float q2 = b.z * b.z, q3 = b.w * b.w;
    float qr0 = r.x * r.x, qr1 = r.y * r.y;
    float4 h;
    h.x = ql0 + ql1 + q0 + q1 + q2;
    h.y = h.x - ql0 + q3;
    h.z = h.y - ql1 + qr0;
    h.w = h.z - q0 + qr1;
    if (!ok) { h.x = 0.f; h.y = 0.f; h.z = 0.f; h.w = 0.f; }
    return h;
}

__global__ __launch_bounds__(224, 3)
void lrn_kernel(const float* __restrict__ x, float* __restrict__ out) {
    extern __shared__ float dynbuf[];          // 2 x 32 x 224 floats
    __shared__ __align__(8) uint64_t mbar[2];

    const int plane = blockIdx.x;                     // n*96 + c
    const int ybase = blockIdx.y * (LRN_TH * LRN_NT); // 0 or 112
    const int tid   = threadIdx.x;
    const int g     = tid % LRN_CG;
    const int rg    = tid / LRN_CG;
    const int g4    = g * 4;
    const bool gl   = (g != 0);
    const bool gr   = (g != LRN_CG - 1);

    const float* __restrict__ px   = x   + (size_t)plane * (LRN_H * LRN_W);
    float*       __restrict__ pout = out + (size_t)plane * (LRN_H * LRN_W);

    if (tid == 0) {
        uint32_t m0 = (uint32_t)__cvta_generic_to_shared(&mbar[0]);
        uint32_t m1 = (uint32_t)__cvta_generic_to_shared(&mbar[1]);
        asm volatile("mbarrier.init.shared.b64 [%0], 1;" :: "r"(m0) : "memory");
        asm volatile("mbarrier.init.shared.b64 [%0], 1;" :: "r"(m1) : "memory");
    }
    __syncthreads();

    // Issue one bulk tile load (thread 0 only). Tile t covers plane rows
    // [ybase + t*28 - 2, +32); clip to [0, 224) and offset the smem dst.
    auto issue_tile = [&](int t) {
        int gr0 = ybase + t * LRN_TH;
        int rs  = gr0 - 2;
        int vlo = rs < 0 ? 0 : rs;
        int vhi = rs + LRN_TR; if (vhi > LRN_H) vhi = LRN_H;
        uint32_t sz = (uint32_t)(vhi - vlo) * LRN_ROWB;
        const float* src = px + (size_t)vlo * LRN_W;
        float* dstp = dynbuf + (t & 1) * LRN_TILE_FLOATS + (vlo - rs) * LRN_W;
        uint32_t dst = (uint32_t)__cvta_generic_to_shared(dstp);
        uint32_t mb  = (uint32_t)__cvta_generic_to_shared(&mbar[t & 1]);
        asm volatile("mbarrier.arrive.expect_tx.shared.b64 _, [%0], %1;"
                     :: "r"(mb), "r"(sz) : "memory");
        asm volatile(
            "cp.async.bulk.shared::cta.global.mbarrier::complete_tx::bytes "
            "[%0], [%1], %2, [%3];"
            :: "r"(dst), "l"(src), "r"(sz), "r"(mb) : "memory");
    };

    if (tid == 0) { issue_tile(0); issue_tile(1); }

    const int ti0 = rg * LRN_R + 2;        // tile-local row of first output

    #pragma unroll 1
    for (int t = 0; t < LRN_NT; ++t) {
        // Wait for tile t (parity = reuse count of its buffer).
        {
            uint32_t mb = (uint32_t)__cvta_generic_to_shared(&mbar[t & 1]);
            uint32_t ph = (uint32_t)((t >> 1) & 1);
            asm volatile(
                "{\n\t.reg .pred P;\n\t"
                "W_%=:\n\t"
                "mbarrier.try_wait.parity.acquire.cta.shared::cta.b64 P, [%0], %1, 0x989680;\n\t"
                "@P bra D_%=;\n\t"
                "bra W_%=;\n\t"
                "D_%=:\n\t}"
                :: "r"(mb), "r"(ph) : "memory");
        }

        const float* buf = dynbuf + (t & 1) * LRN_TILE_FLOATS;
        const int gr0 = ybase + t * LRN_TH;
        const int sr0 = gr0 + rg * LRN_R;       // first output row (always valid)

        // Warmup: h of plane rows sr0-2 .. sr0+1.
        float4 hist[4];
        float4 xr[2];
        float4 tmp;
        const float* rp = buf + (ti0 - 2) * LRN_W;
        hist[0] = hsum_row(rp, g4, gl, gr, (sr0 - 2) >= 0, &tmp);  rp += LRN_W;
        hist[1] = hsum_row(rp, g4, gl, gr, (sr0 - 1) >= 0, &tmp);  rp += LRN_W;
        hist[2] = hsum_row(rp, g4, gl, gr, true, &xr[0]);          rp += LRN_W;
        hist[3] = hsum_row(rp, g4, gl, gr, true, &xr[1]);          rp += LRN_W;

        float4 vs;
        vs.x = hist[0].x + hist[1].x + hist[2].x + hist[3].x;
        vs.y = hist[0].y + hist[1].y + hist[2].y + hist[3].y;
        vs.z = hist[0].z + hist[1].z + hist[2].z + hist[3].z;
        vs.w = hist[0].w + hist[1].w + hist[2].w + hist[3].w;

        float* po = pout + (size_t)sr0 * LRN_W + g4;

        #pragma unroll
        for (int i = 0; i < LRN_R; ++i) {
            float4 xnew;
            bool ok = (sr0 + i + 2) < LRN_H;
            float4 hnew = hsum_row(rp, g4, gl, gr, ok, &xnew);
            rp += LRN_W;

            float4 vf;                        // vertical 5-tap ssq @ row sr0+i
            vf.x = vs.x + hnew.x;
            vf.y = vs.y + hnew.y;
            vf.z = vs.z + hnew.z;
            vf.w = vs.w + hnew.w;

            float4 xa = xr[i & 1];            // raw x @ row sr0+i
            float4 val;
            val.x = xa.x * lrn_norm(vf.x);
            val.y = xa.y * lrn_norm(vf.y);
            val.z = xa.z * lrn_norm(vf.z);
            val.w = xa.w * lrn_norm(vf.w);

            __stcs(reinterpret_cast<float4*>(po), val);
            po += LRN_W;

            float4 hold = hist[i & 3];        // h @ row sr0+i-2
            vs.x = vf.x - hold.x;
            vs.y = vf.y - hold.y;
            vs.z = vf.z - hold.z;
            vs.w = vf.w - hold.w;
            hist[i & 3] = hnew;
            xr[i & 1] = xnew;
        }

        __syncthreads();                      // all lanes done reading buf[t&1]
        if (tid == 0 && t + 2 < LRN_NT) issue_tile(t + 2);
    }
}

extern "C" void kernel_launch(void* const* d_in, const int* in_sizes, int n_in,
                              void* d_out, int out_size) {
    const float* x = (const float*)d_in[0];
    float* out = (float*)d_out;
    (void)in_sizes; (void)n_in; (void)out_size;
    cudaFuncSetAttribute(lrn_kernel,
                         cudaFuncAttributeMaxDynamicSharedMemorySize,
                         2 * LRN_TILE_BYTES);
    dim3 grid(16 * 96, LRN_H / (LRN_TH * LRN_NT));   // 1536 x 2
    lrn_kernel<<<grid, 224, 2 * LRN_TILE_BYTES>>>(x, out);
}